// round 4
// baseline (speedup 1.0000x reference)
#include <cuda_runtime.h>
#include <cuda_bf16.h>

// CRF NLL: B=512, S=1024, T=64.
// inputs: 0 emissions (B,S,T) f32, 1 tags (B,S) i32, 2 mask (B,S) i32,
//         3 start (T) f32, 4 end (T) f32, 5 transitions (T,T) f32
// output: scalar f32 = -(sum_b ll_b) / (sum_b L_b)
//
// Scaled linear-domain forward algorithm, one batch split across TWO warps
// (1 tag-column per lane). w exchanged via smem + named barrier per pair.
// Rescale exponent read from sh_w[pb][0] post-barrier (broadcast LDS) —
// no shfl, no exp/log on the recursion chain.

#define B_ 512
#define S_ 1024
#define T_ 64
#define FULLMASK 0xffffffffu

__device__ float g_ll[B_];
__device__ float g_len[B_];

typedef unsigned long long ull;

__device__ __forceinline__ ull ffma2(ull a, ull b, ull c) {
    ull d;
    asm("fma.rn.f32x2 %0, %1, %2, %3;" : "=l"(d) : "l"(a), "l"(b), "l"(c));
    return d;
}
__device__ __forceinline__ ull fadd2(ull a, ull b) {
    ull d;
    asm("add.rn.f32x2 %0, %1, %2;" : "=l"(d) : "l"(a), "l"(b));
    return d;
}
__device__ __forceinline__ ull pack2(float lo, float hi) {
    ull r;
    asm("mov.b64 %0, {%1, %2};" : "=l"(r) : "f"(lo), "f"(hi));
    return r;
}
__device__ __forceinline__ void unpack2(ull v, float& lo, float& hi) {
    asm("mov.b64 {%0, %1}, %2;" : "=f"(lo), "=f"(hi) : "l"(v));
}

// 256 threads = 8 warps = 4 batch-pairs per block. grid = 128.
__global__ void __launch_bounds__(256) crf_main(
    const float* __restrict__ emis,
    const int* __restrict__ tags,
    const int* __restrict__ mask,
    const float* __restrict__ start,
    const float* __restrict__ endt,
    const float* __restrict__ trans)
{
    __shared__ __align__(16) float sh_w[4][2][T_];   // [pair][buf][col]
    __shared__ float2 sh_red[4][2];                  // [pair][warp-of-pair]

    const int tid   = threadIdx.x;
    const int lane  = tid & 31;
    const int wid   = tid >> 5;
    const int pair  = wid >> 1;        // 0..3
    const int wpair = wid & 1;         // warp within pair
    const int b     = blockIdx.x * 4 + pair;
    const int j     = wpair * 32 + lane;  // this lane's tag column, 0..63
    const int barid = 1 + pair;

    // ---- E column j: Ej[m] = (exp(trans[2m][j]), exp(trans[2m+1][j])) ----
    ull Ej[T_ / 2];
#pragma unroll
    for (int m = 0; m < T_ / 2; m++) {
        float ea = trans[(2 * m) * T_ + j];
        float eb = trans[(2 * m + 1) * T_ + j];
        Ej[m] = pack2(__expf(ea), __expf(eb));
    }

    const int base = b * S_;
    const float* em = emis + (size_t)base * T_;

    // ---- L (each warp computes independently; identical result) ----
    int lp = 0;
#pragma unroll 4
    for (int s = lane; s < S_; s += 32) lp += mask[base + s];
#pragma unroll
    for (int o = 16; o > 0; o >>= 1) lp += __shfl_xor_sync(FULLMASK, lp, o);
    const int L = lp;

    // ---- numerator partial (64-thread stride across the pair) ----
    float num = 0.0f;
#pragma unroll 4
    for (int s = 1 + j; s < S_; s += 64) {
        if (s < L) {
            int tp = tags[base + s - 1];
            int tc = tags[base + s];
            num += trans[tp * T_ + tc] + em[s * T_ + tc];
        }
    }
#pragma unroll
    for (int o = 16; o > 0; o >>= 1) num += __shfl_xor_sync(FULLMASK, num, o);
    if (j == 0) {  // warp 0 lane 0 of the pair
        int tg0 = tags[base];
        int tgl = tags[base + L - 1];
        num += start[tg0] + em[tg0] + endt[tgl];
    }

    // ---- forward recursion init ----
    float w = __expf(start[j] + em[j]);  // s = 0

    // prefetch pipeline, distance 3: F = exp(em[s]); q1 = em[s+1]; q2 = em[s+2]; q3 = em[s+3]
    float e1 = em[1 * T_ + j];
    float e2 = em[2 * T_ + j];
    float e3 = em[3 * T_ + j];
    float e4 = em[4 * T_ + j];
    float F  = __expf(e1);   // for step s=1
    float q1 = e2, q2 = e3, q3 = e4;

    float csum = 0.0f;

    for (int s = 1; s < L; s++) {
        const int pb = s & 1;
        sh_w[pair][pb][j] = w;
        asm volatile("bar.sync %0, %1;" :: "r"(barid), "n"(64) : "memory");

        // rescale exponent from w_{s-1}[0] (broadcast LDS, warp-pair uniform);
        // consumed ~100 cyc later at the w-multiply -> shadowed.
        float w0s = sh_w[pair][pb][0];
        int k = ((__float_as_int(w0s) >> 23) & 0xff) - 127;
        k = max(-126, min(126, k));
        float r = __int_as_float((127 - k) << 23);

        // off-chain: exp(em[s+1]) for next step; advance prefetch
        float Fn = __expf(q1);
        q1 = q2; q2 = q3;
        int sp = s + 4; if (sp > S_ - 1) sp = S_ - 1;
        q3 = em[sp * T_ + j];

        // matvec: v[j] = sum_i w[i] * E[i][j]
        const ulonglong2* qv = (const ulonglong2*)sh_w[pair][pb];
        ull a0 = 0ull, a1 = 0ull, a2 = 0ull, a3 = 0ull;
#pragma unroll
        for (int m = 0; m < 16; m++) {
            ulonglong2 vv = qv[m];  // w[4m .. 4m+3]
            if (m & 1) {
                a2 = ffma2(vv.x, Ej[2 * m], a2);
                a3 = ffma2(vv.y, Ej[2 * m + 1], a3);
            } else {
                a0 = ffma2(vv.x, Ej[2 * m], a0);
                a1 = ffma2(vv.y, Ej[2 * m + 1], a1);
            }
        }
        ull t = fadd2(fadd2(a0, a2), fadd2(a1, a3));
        float tl, th;
        unpack2(t, tl, th);

        w = (tl + th) * (F * r);
        csum += (float)k;
        F = Fn;
    }

    // ---- denominator partial + combine across the pair ----
    float e = w * __expf(endt[j]);
#pragma unroll
    for (int o = 16; o > 0; o >>= 1) e += __shfl_xor_sync(FULLMASK, e, o);

    if (lane == 0) sh_red[pair][wpair] = make_float2(e, num);
    asm volatile("bar.sync %0, %1;" :: "r"(barid), "n"(64) : "memory");

    if (j == 0) {
        float e_tot   = sh_red[pair][0].x + sh_red[pair][1].x;
        float num_tot = sh_red[pair][0].y + sh_red[pair][1].y;
        float den = (float)((double)csum * 0.6931471805599453) + __logf(e_tot);
        g_ll[b]  = num_tot - den;
        g_len[b] = (float)L;
    }
}

__global__ void crf_finalize(float* __restrict__ out) {
    __shared__ float s_ll[16];
    __shared__ float s_ln[16];
    int t = threadIdx.x;  // 512 threads
    float ll = g_ll[t];
    float ln = g_len[t];
#pragma unroll
    for (int o = 16; o > 0; o >>= 1) {
        ll += __shfl_xor_sync(FULLMASK, ll, o);
        ln += __shfl_xor_sync(FULLMASK, ln, o);
    }
    int w = t >> 5;
    if ((t & 31) == 0) { s_ll[w] = ll; s_ln[w] = ln; }
    __syncthreads();
    if (t == 0) {
        float sll = 0.0f, sln = 0.0f;
#pragma unroll
        for (int i = 0; i < 16; i++) { sll += s_ll[i]; sln += s_ln[i]; }
        out[0] = -(sll / sln);
    }
}

extern "C" void kernel_launch(void* const* d_in, const int* in_sizes, int n_in,
                              void* d_out, int out_size) {
    const float* emis  = (const float*)d_in[0];
    const int*   tags  = (const int*)d_in[1];
    const int*   mask  = (const int*)d_in[2];
    const float* start = (const float*)d_in[3];
    const float* endt  = (const float*)d_in[4];
    const float* trans = (const float*)d_in[5];
    float* out = (float*)d_out;

    crf_main<<<B_ / 4, 256>>>(emis, tags, mask, start, endt, trans);
    crf_finalize<<<1, B_>>>(out);
}